// round 3
// baseline (speedup 1.0000x reference)
#include <cuda_runtime.h>
#include <math.h>

#define N_NODES 100000
#define N_EDGES 1250000
#define G_GRAPHS 256
#define IN_DIM 8
#define DIM 64
#define EPS 1e-5f

// ---------------- scratch (device globals; no allocation allowed) ----------
__device__ float g_deg[N_NODES];
__device__ float g_dinv[N_NODES];
__device__ float g_norm[N_EDGES];
__device__ float g_aggx[N_NODES * IN_DIM];
__device__ float g_t[N_NODES * DIM];     // transformed / relu'd features
__device__ float g_agg[N_NODES * DIM];   // aggregation buffer
__device__ float g_h[N_NODES * DIM];     // layer output (post-BN)
__device__ float g_stats[2 * DIM];       // [sum(64), sumsq(64)]
__device__ float g_pooled[G_GRAPHS * DIM];

// ---------------- degree / norm ----------------
__global__ void deg_init_kernel() {
    int i = blockIdx.x * blockDim.x + threadIdx.x;
    if (i < N_NODES) g_deg[i] = 1.0f;  // self-loop weight
}

__global__ void deg_scatter_kernel(const int* __restrict__ ei,
                                   const float* __restrict__ ea) {
    int e = blockIdx.x * blockDim.x + threadIdx.x;
    if (e < N_EDGES) {
        atomicAdd(&g_deg[ei[N_EDGES + e]], ea[2 * e + 1]);
    }
}

__global__ void dinv_kernel() {
    int i = blockIdx.x * blockDim.x + threadIdx.x;
    if (i < N_NODES) {
        float d = g_deg[i];
        g_dinv[i] = (d > 0.0f) ? rsqrtf(d) : 0.0f;
    }
}

__global__ void norm_kernel(const int* __restrict__ ei,
                            const float* __restrict__ ea) {
    int e = blockIdx.x * blockDim.x + threadIdx.x;
    if (e < N_EDGES) {
        int s = ei[e], d = ei[N_EDGES + e];
        g_norm[e] = g_dinv[s] * ea[2 * e + 1] * g_dinv[d];
    }
}

// ---------------- layer 0: aggregate raw x (8-dim) first ----------------
__global__ void agg0_init_kernel(const float* __restrict__ x) {
    int idx = blockIdx.x * blockDim.x + threadIdx.x;
    if (idx < N_NODES * IN_DIM) {
        int n = idx >> 3;
        float di = g_dinv[n];
        g_aggx[idx] = x[idx] * di * di;
    }
}

__global__ void agg0_scatter_kernel(const float* __restrict__ x,
                                    const int* __restrict__ ei) {
    int idx = blockIdx.x * blockDim.x + threadIdx.x;  // E * 2 threads (float4 each)
    if (idx >= N_EDGES * 2) return;
    int e = idx >> 1;
    int q = (idx & 1) << 2;
    int s = ei[e], d = ei[N_EDGES + e];
    float nm = g_norm[e];
    float4 v = *reinterpret_cast<const float4*>(x + (size_t)s * IN_DIM + q);
    float* dp = g_aggx + (size_t)d * IN_DIM + q;
    atomicAdd(dp + 0, v.x * nm);
    atomicAdd(dp + 1, v.y * nm);
    atomicAdd(dp + 2, v.z * nm);
    atomicAdd(dp + 3, v.w * nm);
}

// y = relu(aggx @ W0 + b0) -> g_t
__global__ void gemm0_kernel(const float* __restrict__ W0,
                             const float* __restrict__ b0) {
    __shared__ float sW[IN_DIM][DIM];
    __shared__ float sA[4][IN_DIM];
    int j = threadIdx.x;       // 0..63
    int ty = threadIdx.y;      // 0..3
    int tid = ty * 64 + j;     // 0..255
    for (int i = tid; i < IN_DIM * DIM; i += 256)
        sW[i / DIM][i % DIM] = W0[i];
    int n = blockIdx.x * 4 + ty;
    if (j < IN_DIM) sA[ty][j] = (n < N_NODES) ? g_aggx[(size_t)n * IN_DIM + j] : 0.0f;
    __syncthreads();
    if (n < N_NODES) {
        float acc = b0[j];
#pragma unroll
        for (int k = 0; k < IN_DIM; k++) acc += sA[ty][k] * sW[k][j];
        g_t[(size_t)n * DIM + j] = fmaxf(acc, 0.0f);
    }
}

// ---------------- dense layers: gemm 64x64 ----------------
// g_t[n,j] = sum_k g_h[n,k] * W[k,j]   (globals referenced in DEVICE code only)
__global__ void gemm64_kernel(const float* __restrict__ W) {
    __shared__ float sW[DIM][DIM];   // sW[k][j]
    __shared__ float sH[DIM][DIM];   // sH[k][n] (transposed)
    int tid = threadIdx.x;           // 256 threads
    int n_base = blockIdx.x * 64;
    for (int i = tid; i < 1024; i += 256)
        reinterpret_cast<float4*>(&sW[0][0])[i] =
            reinterpret_cast<const float4*>(W)[i];
    for (int i = tid; i < 1024; i += 256) {
        int n = i >> 4;
        int k4 = (i & 15) << 2;
        float4 v = make_float4(0.f, 0.f, 0.f, 0.f);
        int row = n_base + n;
        if (row < N_NODES)
            v = reinterpret_cast<const float4*>(g_h + (size_t)row * DIM)[i & 15];
        sH[k4 + 0][n] = v.x;
        sH[k4 + 1][n] = v.y;
        sH[k4 + 2][n] = v.z;
        sH[k4 + 3][n] = v.w;
    }
    __syncthreads();
    int tx = tid & 15, ty = tid >> 4;
    int j0 = tx * 4, n0 = ty * 4;
    float acc[4][4];
#pragma unroll
    for (int r = 0; r < 4; r++)
#pragma unroll
        for (int q = 0; q < 4; q++) acc[r][q] = 0.0f;
#pragma unroll
    for (int k = 0; k < DIM; k++) {
        float4 wv = *reinterpret_cast<const float4*>(&sW[k][j0]);
        float4 hv = *reinterpret_cast<const float4*>(&sH[k][n0]);
        acc[0][0] += hv.x * wv.x; acc[0][1] += hv.x * wv.y;
        acc[0][2] += hv.x * wv.z; acc[0][3] += hv.x * wv.w;
        acc[1][0] += hv.y * wv.x; acc[1][1] += hv.y * wv.y;
        acc[1][2] += hv.y * wv.z; acc[1][3] += hv.y * wv.w;
        acc[2][0] += hv.z * wv.x; acc[2][1] += hv.z * wv.y;
        acc[2][2] += hv.z * wv.z; acc[2][3] += hv.z * wv.w;
        acc[3][0] += hv.w * wv.x; acc[3][1] += hv.w * wv.y;
        acc[3][2] += hv.w * wv.z; acc[3][3] += hv.w * wv.w;
    }
#pragma unroll
    for (int r = 0; r < 4; r++) {
        int row = n_base + n0 + r;
        if (row < N_NODES) {
            float4 o = make_float4(acc[r][0], acc[r][1], acc[r][2], acc[r][3]);
            *reinterpret_cast<float4*>(g_t + (size_t)row * DIM + j0) = o;
        }
    }
}

// agg[n,:] = t[n,:] * dinv[n]^2  (self-loop)
__global__ void agg_init_kernel() {
    int idx = blockIdx.x * blockDim.x + threadIdx.x;
    if (idx < N_NODES * DIM) {
        int n = idx >> 6;
        float di = g_dinv[n];
        g_agg[idx] = g_t[idx] * di * di;
    }
}

__global__ void scatter64_kernel(const int* __restrict__ ei) {
    int idx = blockIdx.x * blockDim.x + threadIdx.x;  // E * 16 threads
    if (idx >= N_EDGES * 16) return;
    int e = idx >> 4;
    int q = (idx & 15) << 2;
    int s = ei[e], d = ei[N_EDGES + e];
    float nm = g_norm[e];
    float4 v = *reinterpret_cast<const float4*>(g_t + (size_t)s * DIM + q);
    float* dp = g_agg + (size_t)d * DIM + q;
    atomicAdd(dp + 0, v.x * nm);
    atomicAdd(dp + 1, v.y * nm);
    atomicAdd(dp + 2, v.z * nm);
    atomicAdd(dp + 3, v.w * nm);
}

// y = relu(agg + b) -> g_t
__global__ void bias_relu_kernel(const float* __restrict__ b) {
    int idx = blockIdx.x * blockDim.x + threadIdx.x;
    if (idx < N_NODES * DIM) {
        int j = idx & 63;
        g_t[idx] = fmaxf(g_agg[idx] + b[j], 0.0f);
    }
}

__global__ void zero_stats_kernel() {
    int i = threadIdx.x;
    if (i < 2 * DIM) g_stats[i] = 0.0f;
}

// stats over g_t: grid(256), block(64, 8)
__global__ void stats_kernel() {
    int j = threadIdx.x, ty = threadIdx.y;
    float s = 0.0f, s2 = 0.0f;
    for (int n = blockIdx.x * 8 + ty; n < N_NODES; n += gridDim.x * 8) {
        float v = g_t[(size_t)n * DIM + j];
        s += v;
        s2 += v * v;
    }
    __shared__ float sh[8][DIM], sh2[8][DIM];
    sh[ty][j] = s;
    sh2[ty][j] = s2;
    __syncthreads();
    if (ty == 0) {
#pragma unroll
        for (int r = 1; r < 8; r++) { s += sh[r][j]; s2 += sh2[r][j]; }
        atomicAdd(&g_stats[j], s);
        atomicAdd(&g_stats[DIM + j], s2);
    }
}

// h = gamma*(y-mu)*rsqrt(var+eps)+beta
__global__ void bn_kernel(const float* __restrict__ gamma,
                          const float* __restrict__ beta) {
    int idx = blockIdx.x * blockDim.x + threadIdx.x;
    if (idx < N_NODES * DIM) {
        int j = idx & 63;
        float mu = g_stats[j] * (1.0f / N_NODES);
        float var = g_stats[DIM + j] * (1.0f / N_NODES) - mu * mu;
        float inv = rsqrtf(var + EPS);
        g_h[idx] = gamma[j] * (g_t[idx] - mu) * inv + beta[j];
    }
}

// ---------------- pooling + head ----------------
__global__ void pool_kernel(const int* __restrict__ batch) {
    int g = blockIdx.x;
    int j = threadIdx.x;
    int lo = 0, hi = N_NODES;
    while (lo < hi) { int m = (lo + hi) >> 1; if (batch[m] < g) lo = m + 1; else hi = m; }
    int start = lo;
    lo = start; hi = N_NODES;
    while (lo < hi) { int m = (lo + hi) >> 1; if (batch[m] < g + 1) lo = m + 1; else hi = m; }
    int end = lo;
    float acc = 0.0f;
    for (int i = start; i < end; i++) acc += g_h[(size_t)i * DIM + j];
    g_pooled[g * DIM + j] = acc;
}

__global__ void mlp_kernel(const float* __restrict__ lin1_w,
                           const float* __restrict__ lin1_b,
                           const float* __restrict__ lin2_w,
                           const float* __restrict__ lin2_b,
                           float* __restrict__ out) {
    int g = blockIdx.x;
    int j = threadIdx.x;
    __shared__ float sp[DIM];
    __shared__ float sh[DIM];
    sp[j] = g_pooled[g * DIM + j];
    __syncthreads();
    float acc = lin1_b[j];
#pragma unroll
    for (int k = 0; k < DIM; k++) acc += sp[k] * lin1_w[k * DIM + j];
    sh[j] = fmaxf(acc, 0.0f);
    __syncthreads();
    if (j == 0) {
        float o0 = lin2_b[0], o1 = lin2_b[1];
#pragma unroll
        for (int k = 0; k < DIM; k++) {
            o0 += sh[k] * lin2_w[k * 2 + 0];
            o1 += sh[k] * lin2_w[k * 2 + 1];
        }
        float m = fmaxf(o0, o1);
        float lse = m + logf(expf(o0 - m) + expf(o1 - m));
        out[g * 2 + 0] = o0 - lse;
        out[g * 2 + 1] = o1 - lse;
    }
}

// ---------------- launch ----------------
extern "C" void kernel_launch(void* const* d_in, const int* in_sizes, int n_in,
                              void* d_out, int out_size) {
    const float* x        = (const float*)d_in[0];
    const int*   ei       = (const int*)d_in[1];
    const int*   batch    = (const int*)d_in[2];
    const float* ea       = (const float*)d_in[3];
    const float* W0       = (const float*)d_in[4];
    const float* b0       = (const float*)d_in[5];
    const float* Ws       = (const float*)d_in[6];
    const float* bs       = (const float*)d_in[7];
    const float* gammas   = (const float*)d_in[8];
    const float* betas    = (const float*)d_in[9];
    const float* lin1_w   = (const float*)d_in[10];
    const float* lin1_b   = (const float*)d_in[11];
    const float* lin2_w   = (const float*)d_in[12];
    const float* lin2_b   = (const float*)d_in[13];
    float* out = (float*)d_out;

    const int TB = 256;
    // normalization precompute
    deg_init_kernel<<<(N_NODES + TB - 1) / TB, TB>>>();
    deg_scatter_kernel<<<(N_EDGES + TB - 1) / TB, TB>>>(ei, ea);
    dinv_kernel<<<(N_NODES + TB - 1) / TB, TB>>>();
    norm_kernel<<<(N_EDGES + TB - 1) / TB, TB>>>(ei, ea);

    // ---- layer 0 (aggregate-first on 8-dim x) ----
    agg0_init_kernel<<<(N_NODES * IN_DIM + TB - 1) / TB, TB>>>(x);
    agg0_scatter_kernel<<<(N_EDGES * 2 + TB - 1) / TB, TB>>>(x, ei);
    gemm0_kernel<<<(N_NODES + 3) / 4, dim3(64, 4)>>>(W0, b0);
    zero_stats_kernel<<<1, 128>>>();
    stats_kernel<<<256, dim3(64, 8)>>>();
    bn_kernel<<<(N_NODES * DIM + TB - 1) / TB, TB>>>(gammas + 0 * DIM, betas + 0 * DIM);

    // ---- layers 1, 2 ----
    for (int l = 0; l < 2; l++) {
        gemm64_kernel<<<(N_NODES + 63) / 64, 256>>>(Ws + (size_t)l * DIM * DIM);
        agg_init_kernel<<<(N_NODES * DIM + TB - 1) / TB, TB>>>();
        scatter64_kernel<<<(N_EDGES * 16 + TB - 1) / TB, TB>>>(ei);
        bias_relu_kernel<<<(N_NODES * DIM + TB - 1) / TB, TB>>>(bs + (size_t)l * DIM);
        zero_stats_kernel<<<1, 128>>>();
        stats_kernel<<<256, dim3(64, 8)>>>();
        bn_kernel<<<(N_NODES * DIM + TB - 1) / TB, TB>>>(gammas + (size_t)(l + 1) * DIM,
                                                         betas + (size_t)(l + 1) * DIM);
    }

    // ---- pooling + head ----
    pool_kernel<<<G_GRAPHS, DIM>>>(batch);
    mlp_kernel<<<G_GRAPHS, DIM>>>(lin1_w, lin1_b, lin2_w, lin2_b, out);
}

// round 4
// speedup vs baseline: 2.2516x; 2.2516x over previous
#include <cuda_runtime.h>
#include <math.h>

#define N_NODES 100000
#define N_EDGES 1250000
#define G_GRAPHS 256
#define IN_DIM 8
#define DIM 64
#define EPS 1e-5f
#define NB1 ((N_NODES + 255) / 256)   // 391 scan blocks

// ---------------- scratch (device globals; no allocation allowed) ----------
__device__ float g_deg[N_NODES];
__device__ float g_dinv[N_NODES];
__device__ int   g_cnt[N_NODES];
__device__ int   g_fill[N_NODES];
__device__ int   g_rows[N_NODES];     // per-block exclusive scan
__device__ int   g_bsum[NB1];
__device__ int   g_boff[NB1];
__device__ int   g_rowstart[N_NODES];
__device__ int   g_csr_src[N_EDGES];
__device__ __align__(16) float g_csr_val[N_EDGES];   // dinv[src] * w
__device__ __align__(16) float g_aggx[N_NODES * IN_DIM];
__device__ __align__(16) float g_t[N_NODES * DIM];   // post-activation (pre-BN)
__device__ __align__(16) float g_h[N_NODES * DIM];   // z = BN(t) @ W
__device__ __align__(16) float g_stats[2 * DIM];
__device__ __align__(16) float g_bnA[DIM];
__device__ __align__(16) float g_bnB[DIM];
__device__ __align__(16) float g_pooled[G_GRAPHS * DIM];

// ---------------- init: deg=1 (self-loop), cnt=0, fill=0 ----------------
__global__ void init_kernel() {
    int i = blockIdx.x * blockDim.x + threadIdx.x;
    if (i < N_NODES) { g_deg[i] = 1.0f; g_cnt[i] = 0; g_fill[i] = 0; }
}

// count in-degree (edges) and weighted degree
__global__ void count_kernel(const int* __restrict__ ei,
                             const float* __restrict__ ea) {
    int e = blockIdx.x * blockDim.x + threadIdx.x;
    if (e < N_EDGES) {
        int d = ei[N_EDGES + e];
        atomicAdd(&g_cnt[d], 1);
        atomicAdd(&g_deg[d], ea[2 * e + 1]);
    }
}

__global__ void dinv_kernel() {
    int i = blockIdx.x * blockDim.x + threadIdx.x;
    if (i < N_NODES) {
        float d = g_deg[i];
        g_dinv[i] = (d > 0.0f) ? rsqrtf(d) : 0.0f;
    }
}

// ---------------- 3-step exclusive scan of g_cnt -> g_rowstart ----------
__global__ void scan1_kernel() {
    __shared__ int sdata[256];
    int t = threadIdx.x;
    int n = blockIdx.x * 256 + t;
    int v = (n < N_NODES) ? g_cnt[n] : 0;
    int val = v;
    sdata[t] = val;
    __syncthreads();
    for (int off = 1; off < 256; off <<= 1) {
        int y = (t >= off) ? sdata[t - off] : 0;
        __syncthreads();
        val += y;
        sdata[t] = val;
        __syncthreads();
    }
    if (n < N_NODES) g_rows[n] = val - v;   // exclusive
    if (t == 255) g_bsum[blockIdx.x] = val; // block total
}

__global__ void scan2_kernel() {
    __shared__ int sdata[512];
    int t = threadIdx.x;
    int v = (t < NB1) ? g_bsum[t] : 0;
    int val = v;
    sdata[t] = val;
    __syncthreads();
    for (int off = 1; off < 512; off <<= 1) {
        int y = (t >= off) ? sdata[t - off] : 0;
        __syncthreads();
        val += y;
        sdata[t] = val;
        __syncthreads();
    }
    if (t < NB1) g_boff[t] = val - v;
}

__global__ void scan3_kernel() {
    int n = blockIdx.x * 256 + threadIdx.x;
    if (n < N_NODES) g_rowstart[n] = g_rows[n] + g_boff[blockIdx.x];
}

// fill CSR: src index + premultiplied value dinv[src]*w
__global__ void fill_kernel(const int* __restrict__ ei,
                            const float* __restrict__ ea) {
    int e = blockIdx.x * blockDim.x + threadIdx.x;
    if (e < N_EDGES) {
        int s = ei[e], d = ei[N_EDGES + e];
        int pos = g_rowstart[d] + atomicAdd(&g_fill[d], 1);
        g_csr_src[pos] = s;
        g_csr_val[pos] = g_dinv[s] * ea[2 * e + 1];
    }
}

// ---------------- layer 0: gather raw x (8-dim) ----------------
// 32 nodes per block, 8 threads per node
__global__ void gather8_kernel(const float* __restrict__ x) {
    int tid = threadIdx.x;
    int j = tid & 7;
    int n = blockIdx.x * 32 + (tid >> 3);
    if (n >= N_NODES) return;
    int start = g_rowstart[n];
    int end = start + g_cnt[n];
    float acc = 0.0f;
    int e = start;
    for (; e + 1 < end; e += 2) {
        int s0 = g_csr_src[e], s1 = g_csr_src[e + 1];
        float v0 = g_csr_val[e], v1 = g_csr_val[e + 1];
        acc += v0 * x[(size_t)s0 * IN_DIM + j] + v1 * x[(size_t)s1 * IN_DIM + j];
    }
    if (e < end) acc += g_csr_val[e] * x[(size_t)g_csr_src[e] * IN_DIM + j];
    float di = g_dinv[n];
    g_aggx[(size_t)n * IN_DIM + j] = di * acc + di * di * x[(size_t)n * IN_DIM + j];
}

// t = relu(aggx @ W0 + b0)
__global__ void gemm0_kernel(const float* __restrict__ W0,
                             const float* __restrict__ b0) {
    __shared__ float sW[IN_DIM][DIM];
    __shared__ float sA[4][IN_DIM];
    int j = threadIdx.x;       // 0..63
    int ty = threadIdx.y;      // 0..3
    int tid = ty * 64 + j;     // 0..255
    for (int i = tid; i < IN_DIM * DIM; i += 256)
        sW[i / DIM][i % DIM] = W0[i];
    int n = blockIdx.x * 4 + ty;
    if (j < IN_DIM) sA[ty][j] = (n < N_NODES) ? g_aggx[(size_t)n * IN_DIM + j] : 0.0f;
    __syncthreads();
    if (n < N_NODES) {
        float acc = b0[j];
#pragma unroll
        for (int k = 0; k < IN_DIM; k++) acc += sA[ty][k] * sW[k][j];
        g_t[(size_t)n * DIM + j] = fmaxf(acc, 0.0f);
    }
}

// ---------------- dense layers ----------------
// z[n,j] = sum_k BN(t[n,k]) * W[k,j], BN applied via per-feature affine A,B
__global__ void gemm64_kernel(const float* __restrict__ W) {
    __shared__ float sW[DIM][DIM];   // sW[k][j]
    __shared__ float sH[DIM][DIM];   // sH[k][n] (transposed, BN applied)
    int tid = threadIdx.x;           // 256 threads
    int n_base = blockIdx.x * 64;
    for (int i = tid; i < 1024; i += 256)
        reinterpret_cast<float4*>(&sW[0][0])[i] =
            reinterpret_cast<const float4*>(W)[i];
    for (int i = tid; i < 1024; i += 256) {
        int n = i >> 4;
        int k4 = (i & 15) << 2;
        float4 v = make_float4(0.f, 0.f, 0.f, 0.f);
        int row = n_base + n;
        if (row < N_NODES)
            v = reinterpret_cast<const float4*>(g_t + (size_t)row * DIM)[i & 15];
        float4 A = *reinterpret_cast<const float4*>(g_bnA + k4);
        float4 B = *reinterpret_cast<const float4*>(g_bnB + k4);
        sH[k4 + 0][n] = A.x * v.x + B.x;
        sH[k4 + 1][n] = A.y * v.y + B.y;
        sH[k4 + 2][n] = A.z * v.z + B.z;
        sH[k4 + 3][n] = A.w * v.w + B.w;
    }
    __syncthreads();
    int tx = tid & 15, ty = tid >> 4;
    int j0 = tx * 4, n0 = ty * 4;
    float acc[4][4];
#pragma unroll
    for (int r = 0; r < 4; r++)
#pragma unroll
        for (int q = 0; q < 4; q++) acc[r][q] = 0.0f;
#pragma unroll
    for (int k = 0; k < DIM; k++) {
        float4 wv = *reinterpret_cast<const float4*>(&sW[k][j0]);
        float4 hv = *reinterpret_cast<const float4*>(&sH[k][n0]);
        acc[0][0] += hv.x * wv.x; acc[0][1] += hv.x * wv.y;
        acc[0][2] += hv.x * wv.z; acc[0][3] += hv.x * wv.w;
        acc[1][0] += hv.y * wv.x; acc[1][1] += hv.y * wv.y;
        acc[1][2] += hv.y * wv.z; acc[1][3] += hv.y * wv.w;
        acc[2][0] += hv.z * wv.x; acc[2][1] += hv.z * wv.y;
        acc[2][2] += hv.z * wv.z; acc[2][3] += hv.z * wv.w;
        acc[3][0] += hv.w * wv.x; acc[3][1] += hv.w * wv.y;
        acc[3][2] += hv.w * wv.z; acc[3][3] += hv.w * wv.w;
    }
#pragma unroll
    for (int r = 0; r < 4; r++) {
        int row = n_base + n0 + r;
        if (row < N_NODES) {
            float4 o = make_float4(acc[r][0], acc[r][1], acc[r][2], acc[r][3]);
            *reinterpret_cast<float4*>(g_h + (size_t)row * DIM + j0) = o;
        }
    }
}

// gather over CSR + self-loop + bias + relu, z (g_h) -> t (g_t)
// 16 nodes per block, 16 threads per node (float4 lanes)
__global__ void gather64_kernel(const float* __restrict__ bias) {
    int tid = threadIdx.x;
    int lane = tid & 15;
    int j4 = lane << 2;
    int n = blockIdx.x * 16 + (tid >> 4);
    if (n >= N_NODES) return;
    int start = g_rowstart[n];
    int end = start + g_cnt[n];
    float4 acc = make_float4(0.f, 0.f, 0.f, 0.f);
    int e = start;
    for (; e + 1 < end; e += 2) {
        int s0 = g_csr_src[e], s1 = g_csr_src[e + 1];
        float v0 = g_csr_val[e], v1 = g_csr_val[e + 1];
        float4 h0 = *reinterpret_cast<const float4*>(g_h + (size_t)s0 * DIM + j4);
        float4 h1 = *reinterpret_cast<const float4*>(g_h + (size_t)s1 * DIM + j4);
        acc.x += v0 * h0.x + v1 * h1.x;
        acc.y += v0 * h0.y + v1 * h1.y;
        acc.z += v0 * h0.z + v1 * h1.z;
        acc.w += v0 * h0.w + v1 * h1.w;
    }
    if (e < end) {
        int s0 = g_csr_src[e];
        float v0 = g_csr_val[e];
        float4 h0 = *reinterpret_cast<const float4*>(g_h + (size_t)s0 * DIM + j4);
        acc.x += v0 * h0.x; acc.y += v0 * h0.y;
        acc.z += v0 * h0.z; acc.w += v0 * h0.w;
    }
    float di = g_dinv[n];
    float di2 = di * di;
    float4 self = *reinterpret_cast<const float4*>(g_h + (size_t)n * DIM + j4);
    float4 b = *reinterpret_cast<const float4*>(bias + j4);
    float4 r;
    r.x = fmaxf(di * acc.x + di2 * self.x + b.x, 0.f);
    r.y = fmaxf(di * acc.y + di2 * self.y + b.y, 0.f);
    r.z = fmaxf(di * acc.z + di2 * self.z + b.z, 0.f);
    r.w = fmaxf(di * acc.w + di2 * self.w + b.w, 0.f);
    *reinterpret_cast<float4*>(g_t + (size_t)n * DIM + j4) = r;
}

// ---------------- BN stats ----------------
__global__ void zero_stats_kernel() {
    int i = threadIdx.x;
    if (i < 2 * DIM) g_stats[i] = 0.0f;
}

__global__ void stats_kernel() {
    int j = threadIdx.x, ty = threadIdx.y;
    float s = 0.0f, s2 = 0.0f;
    for (int n = blockIdx.x * 8 + ty; n < N_NODES; n += gridDim.x * 8) {
        float v = g_t[(size_t)n * DIM + j];
        s += v;
        s2 += v * v;
    }
    __shared__ float sh[8][DIM], sh2[8][DIM];
    sh[ty][j] = s;
    sh2[ty][j] = s2;
    __syncthreads();
    if (ty == 0) {
#pragma unroll
        for (int r = 1; r < 8; r++) { s += sh[r][j]; s2 += sh2[r][j]; }
        atomicAdd(&g_stats[j], s);
        atomicAdd(&g_stats[DIM + j], s2);
    }
}

// affine: BN(t) = A*t + B
__global__ void bn_coef_kernel(const float* __restrict__ gamma,
                               const float* __restrict__ beta) {
    int j = threadIdx.x;
    float mu = g_stats[j] * (1.0f / N_NODES);
    float var = g_stats[DIM + j] * (1.0f / N_NODES) - mu * mu;
    float inv = rsqrtf(var + EPS);
    float A = gamma[j] * inv;
    g_bnA[j] = A;
    g_bnB[j] = beta[j] - mu * A;
}

// ---------------- pooling (applies final BN affine) + head ----------------
__global__ void pool_kernel(const int* __restrict__ batch) {
    int g = blockIdx.x;
    int j = threadIdx.x;   // 0..63
    int ty = threadIdx.y;  // 0..3
    int lo = 0, hi = N_NODES;
    while (lo < hi) { int m = (lo + hi) >> 1; if (batch[m] < g) lo = m + 1; else hi = m; }
    int start = lo;
    lo = start; hi = N_NODES;
    while (lo < hi) { int m = (lo + hi) >> 1; if (batch[m] < g + 1) lo = m + 1; else hi = m; }
    int end = lo;
    float acc = 0.0f;
    for (int i = start + ty; i < end; i += 4) acc += g_t[(size_t)i * DIM + j];
    __shared__ float sh[4][DIM];
    sh[ty][j] = acc;
    __syncthreads();
    if (ty == 0) {
        float s = sh[0][j] + sh[1][j] + sh[2][j] + sh[3][j];
        // sum of (A*t+B) = A*sum(t) + B*count
        g_pooled[g * DIM + j] = g_bnA[j] * s + g_bnB[j] * (float)(end - start);
    }
}

__global__ void mlp_kernel(const float* __restrict__ lin1_w,
                           const float* __restrict__ lin1_b,
                           const float* __restrict__ lin2_w,
                           const float* __restrict__ lin2_b,
                           float* __restrict__ out) {
    int g = blockIdx.x;
    int j = threadIdx.x;
    __shared__ float sp[DIM];
    __shared__ float sh[DIM];
    sp[j] = g_pooled[g * DIM + j];
    __syncthreads();
    float acc = lin1_b[j];
#pragma unroll
    for (int k = 0; k < DIM; k++) acc += sp[k] * lin1_w[k * DIM + j];
    sh[j] = fmaxf(acc, 0.0f);
    __syncthreads();
    if (j == 0) {
        float o0 = lin2_b[0], o1 = lin2_b[1];
#pragma unroll
        for (int k = 0; k < DIM; k++) {
            o0 += sh[k] * lin2_w[k * 2 + 0];
            o1 += sh[k] * lin2_w[k * 2 + 1];
        }
        float m = fmaxf(o0, o1);
        float lse = m + logf(expf(o0 - m) + expf(o1 - m));
        out[g * 2 + 0] = o0 - lse;
        out[g * 2 + 1] = o1 - lse;
    }
}

// ---------------- launch ----------------
extern "C" void kernel_launch(void* const* d_in, const int* in_sizes, int n_in,
                              void* d_out, int out_size) {
    const float* x        = (const float*)d_in[0];
    const int*   ei       = (const int*)d_in[1];
    const int*   batch    = (const int*)d_in[2];
    const float* ea       = (const float*)d_in[3];
    const float* W0       = (const float*)d_in[4];
    const float* b0       = (const float*)d_in[5];
    const float* Ws       = (const float*)d_in[6];
    const float* bs       = (const float*)d_in[7];
    const float* gammas   = (const float*)d_in[8];
    const float* betas    = (const float*)d_in[9];
    const float* lin1_w   = (const float*)d_in[10];
    const float* lin1_b   = (const float*)d_in[11];
    const float* lin2_w   = (const float*)d_in[12];
    const float* lin2_b   = (const float*)d_in[13];
    float* out = (float*)d_out;

    const int TB = 256;
    const int EB = (N_EDGES + TB - 1) / TB;

    // CSR build + normalization
    init_kernel<<<NB1, TB>>>();
    count_kernel<<<EB, TB>>>(ei, ea);
    dinv_kernel<<<NB1, TB>>>();
    scan1_kernel<<<NB1, TB>>>();
    scan2_kernel<<<1, 512>>>();
    scan3_kernel<<<NB1, TB>>>();
    fill_kernel<<<EB, TB>>>(ei, ea);

    // layer 0: gather x, then transform
    gather8_kernel<<<(N_NODES + 31) / 32, TB>>>(x);
    gemm0_kernel<<<(N_NODES + 3) / 4, dim3(64, 4)>>>(W0, b0);
    zero_stats_kernel<<<1, 128>>>();
    stats_kernel<<<256, dim3(64, 8)>>>();
    bn_coef_kernel<<<1, 64>>>(gammas, betas);

    // layers 1, 2
    for (int l = 0; l < 2; l++) {
        gemm64_kernel<<<(N_NODES + 63) / 64, 256>>>(Ws + (size_t)l * DIM * DIM);
        gather64_kernel<<<(N_NODES + 15) / 16, 256>>>(bs + (size_t)l * DIM);
        zero_stats_kernel<<<1, 128>>>();
        stats_kernel<<<256, dim3(64, 8)>>>();
        bn_coef_kernel<<<1, 64>>>(gammas + (size_t)(l + 1) * DIM,
                                  betas + (size_t)(l + 1) * DIM);
    }

    // pooling (final BN affine fused) + head
    pool_kernel<<<G_GRAPHS, dim3(64, 4)>>>(batch);
    mlp_kernel<<<G_GRAPHS, 64>>>(lin1_w, lin1_b, lin2_w, lin2_b, out);
}

// round 6
// speedup vs baseline: 2.6294x; 1.1678x over previous
#include <cuda_runtime.h>
#include <math.h>

#define N_NODES 100000
#define N_EDGES 1250000
#define G_GRAPHS 256
#define IN_DIM 8
#define DIM 64
#define EPS 1e-5f
#define NB1 ((N_NODES + 255) / 256)   // 391 scan blocks

// ---------------- scratch (device globals; no allocation allowed) ----------
__device__ float g_deg[N_NODES];
__device__ float g_dinv[N_NODES];
__device__ int   g_cnt[N_NODES];
__device__ int   g_fill[N_NODES];
__device__ int   g_rows[N_NODES];
__device__ int   g_bsum[NB1];
__device__ int   g_boff[NB1];
__device__ int   g_rowstart[N_NODES];
__device__ __align__(16) int2  g_csr[N_EDGES];       // {src, val bits}
__device__ __align__(16) float g_aggx[N_NODES * IN_DIM];
__device__ __align__(16) float g_t[N_NODES * DIM];   // post-activation (pre-BN)
__device__ __align__(16) float g_h[N_NODES * DIM];   // z = BN(t) @ W
__device__ __align__(16) float g_stats[2 * DIM];     // zero-init; self-zeroing protocol
__device__ __align__(16) float g_bnA[DIM];
__device__ __align__(16) float g_bnB[DIM];
__device__ __align__(16) float g_pooled[G_GRAPHS * DIM];

// ---------------- init: deg=1 (self-loop), cnt=0, fill=0 ----------------
__global__ void init_kernel() {
    int i = blockIdx.x * blockDim.x + threadIdx.x;
    if (i < N_NODES) { g_deg[i] = 1.0f; g_cnt[i] = 0; g_fill[i] = 0; }
}

__global__ void count_kernel(const int* __restrict__ ei,
                             const float* __restrict__ ea) {
    int e = blockIdx.x * blockDim.x + threadIdx.x;
    if (e < N_EDGES) {
        int d = ei[N_EDGES + e];
        atomicAdd(&g_cnt[d], 1);
        atomicAdd(&g_deg[d], ea[2 * e + 1]);
    }
}

// ---------------- scan of g_cnt -> g_rowstart (+ dinv fused) ----------
__global__ void scan1_kernel() {
    __shared__ int sdata[256];
    int t = threadIdx.x;
    int n = blockIdx.x * 256 + t;
    int v = (n < N_NODES) ? g_cnt[n] : 0;
    int val = v;
    sdata[t] = val;
    __syncthreads();
    for (int off = 1; off < 256; off <<= 1) {
        int y = (t >= off) ? sdata[t - off] : 0;
        __syncthreads();
        val += y;
        sdata[t] = val;
        __syncthreads();
    }
    if (n < N_NODES) {
        g_rows[n] = val - v;   // exclusive
        float d = g_deg[n];
        g_dinv[n] = (d > 0.0f) ? rsqrtf(d) : 0.0f;
    }
    if (t == 255) g_bsum[blockIdx.x] = val;
}

__global__ void scan2_kernel() {
    __shared__ int sdata[512];
    int t = threadIdx.x;
    int v = (t < NB1) ? g_bsum[t] : 0;
    int val = v;
    sdata[t] = val;
    __syncthreads();
    for (int off = 1; off < 512; off <<= 1) {
        int y = (t >= off) ? sdata[t - off] : 0;
        __syncthreads();
        val += y;
        sdata[t] = val;
        __syncthreads();
    }
    if (t < NB1) g_boff[t] = val - v;
}

__global__ void scan3_kernel() {
    int n = blockIdx.x * 256 + threadIdx.x;
    if (n < N_NODES) g_rowstart[n] = g_rows[n] + g_boff[blockIdx.x];
}

__global__ void fill_kernel(const int* __restrict__ ei,
                            const float* __restrict__ ea) {
    int e = blockIdx.x * blockDim.x + threadIdx.x;
    if (e < N_EDGES) {
        int s = ei[e], d = ei[N_EDGES + e];
        int pos = g_rowstart[d] + atomicAdd(&g_fill[d], 1);
        g_csr[pos] = make_int2(s, __float_as_int(g_dinv[s] * ea[2 * e + 1]));
    }
}

// ---------------- layer 0: gather raw x (8-dim) ----------------
// 32 nodes per block (exact: 100000 = 3125*32), 8 threads per node
__global__ void gather8_kernel(const float* __restrict__ x) {
    int tid = threadIdx.x;
    int j = tid & 7;
    int n = blockIdx.x * 32 + (tid >> 3);
    int start = g_rowstart[n];
    int end = start + g_cnt[n];
    float acc = 0.0f;
    int e = start;
    for (; e + 1 < end; e += 2) {
        int2 c0 = g_csr[e], c1 = g_csr[e + 1];
        acc += __int_as_float(c0.y) * x[(size_t)c0.x * IN_DIM + j]
             + __int_as_float(c1.y) * x[(size_t)c1.x * IN_DIM + j];
    }
    if (e < end) {
        int2 c0 = g_csr[e];
        acc += __int_as_float(c0.y) * x[(size_t)c0.x * IN_DIM + j];
    }
    float di = g_dinv[n];
    g_aggx[(size_t)n * IN_DIM + j] = di * acc + di * di * x[(size_t)n * IN_DIM + j];
}

// t = relu(aggx @ W0 + b0), stats fused. 64 nodes/block, block(64,4)
__global__ void gemm0_kernel(const float* __restrict__ W0,
                             const float* __restrict__ b0) {
    __shared__ float sW[IN_DIM][DIM];
    __shared__ float sA[64][IN_DIM];
    __shared__ float red[4][DIM], red2[4][DIM];
    int j = threadIdx.x;       // 0..63
    int ty = threadIdx.y;      // 0..3
    int tid = ty * 64 + j;     // 0..255
    int n_base = blockIdx.x * 64;
    for (int i = tid; i < IN_DIM * DIM; i += 256)
        sW[i >> 6][i & 63] = W0[i];
    for (int i = tid; i < 64 * IN_DIM; i += 256) {
        int nn = n_base + (i >> 3);
        sA[i >> 3][i & 7] = (nn < N_NODES) ? g_aggx[(size_t)nn * IN_DIM + (i & 7)] : 0.0f;
    }
    __syncthreads();
    float bj = b0[j];
    float s = 0.0f, s2 = 0.0f;
    for (int i = ty; i < 64; i += 4) {
        int n = n_base + i;
        if (n < N_NODES) {
            float acc = bj;
#pragma unroll
            for (int k = 0; k < IN_DIM; k++) acc += sA[i][k] * sW[k][j];
            float r = fmaxf(acc, 0.0f);
            g_t[(size_t)n * DIM + j] = r;
            s += r;
            s2 += r * r;
        }
    }
    red[ty][j] = s;
    red2[ty][j] = s2;
    __syncthreads();
    if (ty == 0) {
        float t0 = red[0][j] + red[1][j] + red[2][j] + red[3][j];
        atomicAdd(&g_stats[j], t0);
    } else if (ty == 1) {
        float t1 = red2[0][j] + red2[1][j] + red2[2][j] + red2[3][j];
        atomicAdd(&g_stats[DIM + j], t1);
    }
}

// ---------------- dense layers ----------------
// z[n,j] = sum_k (A[k]*t[n,k]+B[k]) * W[k,j]
__global__ void gemm64_kernel(const float* __restrict__ W) {
    __shared__ float sW[DIM][DIM];
    __shared__ float sH[DIM][DIM];
    int tid = threadIdx.x;           // 256 threads
    int n_base = blockIdx.x * 64;
    for (int i = tid; i < 1024; i += 256)
        reinterpret_cast<float4*>(&sW[0][0])[i] =
            reinterpret_cast<const float4*>(W)[i];
    for (int i = tid; i < 1024; i += 256) {
        int n = i >> 4;
        int k4 = (i & 15) << 2;
        float4 v = make_float4(0.f, 0.f, 0.f, 0.f);
        int row = n_base + n;
        if (row < N_NODES)
            v = reinterpret_cast<const float4*>(g_t + (size_t)row * DIM)[i & 15];
        float4 A = *reinterpret_cast<const float4*>(g_bnA + k4);
        float4 B = *reinterpret_cast<const float4*>(g_bnB + k4);
        sH[k4 + 0][n] = A.x * v.x + B.x;
        sH[k4 + 1][n] = A.y * v.y + B.y;
        sH[k4 + 2][n] = A.z * v.z + B.z;
        sH[k4 + 3][n] = A.w * v.w + B.w;
    }
    __syncthreads();
    int tx = tid & 15, ty = tid >> 4;
    int j0 = tx * 4, n0 = ty * 4;
    float acc[4][4];
#pragma unroll
    for (int r = 0; r < 4; r++)
#pragma unroll
        for (int q = 0; q < 4; q++) acc[r][q] = 0.0f;
#pragma unroll
    for (int k = 0; k < DIM; k++) {
        float4 wv = *reinterpret_cast<const float4*>(&sW[k][j0]);
        float4 hv = *reinterpret_cast<const float4*>(&sH[k][n0]);
        acc[0][0] += hv.x * wv.x; acc[0][1] += hv.x * wv.y;
        acc[0][2] += hv.x * wv.z; acc[0][3] += hv.x * wv.w;
        acc[1][0] += hv.y * wv.x; acc[1][1] += hv.y * wv.y;
        acc[1][2] += hv.y * wv.z; acc[1][3] += hv.y * wv.w;
        acc[2][0] += hv.z * wv.x; acc[2][1] += hv.z * wv.y;
        acc[2][2] += hv.z * wv.z; acc[2][3] += hv.z * wv.w;
        acc[3][0] += hv.w * wv.x; acc[3][1] += hv.w * wv.y;
        acc[3][2] += hv.w * wv.z; acc[3][3] += hv.w * wv.w;
    }
#pragma unroll
    for (int r = 0; r < 4; r++) {
        int row = n_base + n0 + r;
        if (row < N_NODES) {
            float4 o = make_float4(acc[r][0], acc[r][1], acc[r][2], acc[r][3]);
            *reinterpret_cast<float4*>(g_h + (size_t)row * DIM + j0) = o;
        }
    }
}

// gather + self-loop + bias + relu + stats. 32 nodes/block (exact), 512 threads
__global__ void gather64_kernel(const float* __restrict__ bias) {
    int tid = threadIdx.x;
    int lane = tid & 15;
    int j4 = lane << 2;
    int ln = tid >> 4;                 // 0..31 local node
    int n = blockIdx.x * 32 + ln;      // always < N (100000 = 3125*32)
    int start = g_rowstart[n];
    int end = start + g_cnt[n];
    float4 acc = make_float4(0.f, 0.f, 0.f, 0.f);
    int e = start;
    for (; e + 3 < end; e += 4) {
        int2 c0 = g_csr[e],     c1 = g_csr[e + 1];
        int2 c2 = g_csr[e + 2], c3 = g_csr[e + 3];
        float4 h0 = *reinterpret_cast<const float4*>(g_h + (size_t)c0.x * DIM + j4);
        float4 h1 = *reinterpret_cast<const float4*>(g_h + (size_t)c1.x * DIM + j4);
        float4 h2 = *reinterpret_cast<const float4*>(g_h + (size_t)c2.x * DIM + j4);
        float4 h3 = *reinterpret_cast<const float4*>(g_h + (size_t)c3.x * DIM + j4);
        float v0 = __int_as_float(c0.y), v1 = __int_as_float(c1.y);
        float v2 = __int_as_float(c2.y), v3 = __int_as_float(c3.y);
        acc.x += v0 * h0.x + v1 * h1.x + v2 * h2.x + v3 * h3.x;
        acc.y += v0 * h0.y + v1 * h1.y + v2 * h2.y + v3 * h3.y;
        acc.z += v0 * h0.z + v1 * h1.z + v2 * h2.z + v3 * h3.z;
        acc.w += v0 * h0.w + v1 * h1.w + v2 * h2.w + v3 * h3.w;
    }
    for (; e < end; e++) {
        int2 c0 = g_csr[e];
        float v0 = __int_as_float(c0.y);
        float4 h0 = *reinterpret_cast<const float4*>(g_h + (size_t)c0.x * DIM + j4);
        acc.x += v0 * h0.x; acc.y += v0 * h0.y;
        acc.z += v0 * h0.z; acc.w += v0 * h0.w;
    }
    float di = g_dinv[n];
    float di2 = di * di;
    float4 self = *reinterpret_cast<const float4*>(g_h + (size_t)n * DIM + j4);
    float4 b = *reinterpret_cast<const float4*>(bias + j4);
    float4 r;
    r.x = fmaxf(di * acc.x + di2 * self.x + b.x, 0.f);
    r.y = fmaxf(di * acc.y + di2 * self.y + b.y, 0.f);
    r.z = fmaxf(di * acc.z + di2 * self.z + b.z, 0.f);
    r.w = fmaxf(di * acc.w + di2 * self.w + b.w, 0.f);
    *reinterpret_cast<float4*>(g_t + (size_t)n * DIM + j4) = r;

    // fused stats
    __shared__ float ss[32][DIM], ss2[32][DIM];
    *reinterpret_cast<float4*>(&ss[ln][j4]) = r;
    float4 rq = make_float4(r.x * r.x, r.y * r.y, r.z * r.z, r.w * r.w);
    *reinterpret_cast<float4*>(&ss2[ln][j4]) = rq;
    __syncthreads();
    if (tid < DIM) {
        int j = tid;
        float s = 0.0f;
#pragma unroll
        for (int i = 0; i < 32; i++) s += ss[i][j];
        atomicAdd(&g_stats[j], s);
    } else if (tid < 2 * DIM) {
        int j = tid - DIM;
        float s2 = 0.0f;
#pragma unroll
        for (int i = 0; i < 32; i++) s2 += ss2[i][j];
        atomicAdd(&g_stats[DIM + j], s2);
    }
}

// affine: BN(t) = A*t + B ; zeroes stats for next accumulation (self-zeroing)
__global__ void bn_coef_kernel(const float* __restrict__ gamma,
                               const float* __restrict__ beta) {
    int j = threadIdx.x;
    float mu = g_stats[j] * (1.0f / N_NODES);
    float var = g_stats[DIM + j] * (1.0f / N_NODES) - mu * mu;
    float inv = rsqrtf(var + EPS);
    float A = gamma[j] * inv;
    g_bnA[j] = A;
    g_bnB[j] = beta[j] - mu * A;
    g_stats[j] = 0.0f;
    g_stats[DIM + j] = 0.0f;
}

// ---------------- pooling (applies final BN affine) + head ----------------
__global__ void pool_kernel(const int* __restrict__ batch) {
    int g = blockIdx.x;
    int j = threadIdx.x;   // 0..63
    int ty = threadIdx.y;  // 0..3
    int lo = 0, hi = N_NODES;
    while (lo < hi) { int m = (lo + hi) >> 1; if (batch[m] < g) lo = m + 1; else hi = m; }
    int start = lo;
    lo = start; hi = N_NODES;
    while (lo < hi) { int m = (lo + hi) >> 1; if (batch[m] < g + 1) lo = m + 1; else hi = m; }
    int end = lo;
    float acc = 0.0f;
    for (int i = start + ty; i < end; i += 4) acc += g_t[(size_t)i * DIM + j];
    __shared__ float sh[4][DIM];
    sh[ty][j] = acc;
    __syncthreads();
    if (ty == 0) {
        float s = sh[0][j] + sh[1][j] + sh[2][j] + sh[3][j];
        g_pooled[g * DIM + j] = g_bnA[j] * s + g_bnB[j] * (float)(end - start);
    }
}

__global__ void mlp_kernel(const float* __restrict__ lin1_w,
                           const float* __restrict__ lin1_b,
                           const float* __restrict__ lin2_w,
                           const float* __restrict__ lin2_b,
                           float* __restrict__ out) {
    int g = blockIdx.x;
    int j = threadIdx.x;
    __shared__ float sp[DIM];
    __shared__ float sh[DIM];
    sp[j] = g_pooled[g * DIM + j];
    __syncthreads();
    float acc = lin1_b[j];
#pragma unroll
    for (int k = 0; k < DIM; k++) acc += sp[k] * lin1_w[k * DIM + j];
    sh[j] = fmaxf(acc, 0.0f);
    __syncthreads();
    if (j == 0) {
        float o0 = lin2_b[0], o1 = lin2_b[1];
#pragma unroll
        for (int k = 0; k < DIM; k++) {
            o0 += sh[k] * lin2_w[k * 2 + 0];
            o1 += sh[k] * lin2_w[k * 2 + 1];
        }
        float m = fmaxf(o0, o1);
        float lse = m + logf(expf(o0 - m) + expf(o1 - m));
        out[g * 2 + 0] = o0 - lse;
        out[g * 2 + 1] = o1 - lse;
    }
}

// ---------------- launch ----------------
extern "C" void kernel_launch(void* const* d_in, const int* in_sizes, int n_in,
                              void* d_out, int out_size) {
    const float* x        = (const float*)d_in[0];
    const int*   ei       = (const int*)d_in[1];
    const int*   batch    = (const int*)d_in[2];
    const float* ea       = (const float*)d_in[3];
    const float* W0       = (const float*)d_in[4];
    const float* b0       = (const float*)d_in[5];
    const float* Ws       = (const float*)d_in[6];
    const float* bs       = (const float*)d_in[7];
    const float* gammas   = (const float*)d_in[8];
    const float* betas    = (const float*)d_in[9];
    const float* lin1_w   = (const float*)d_in[10];
    const float* lin1_b   = (const float*)d_in[11];
    const float* lin2_w   = (const float*)d_in[12];
    const float* lin2_b   = (const float*)d_in[13];
    float* out = (float*)d_out;

    const int TB = 256;
    const int EB = (N_EDGES + TB - 1) / TB;

    // CSR build + normalization
    init_kernel<<<NB1, TB>>>();
    count_kernel<<<EB, TB>>>(ei, ea);
    scan1_kernel<<<NB1, TB>>>();
    scan2_kernel<<<1, 512>>>();
    scan3_kernel<<<NB1, TB>>>();
    fill_kernel<<<EB, TB>>>(ei, ea);

    // layer 0
    gather8_kernel<<<N_NODES / 32, TB>>>(x);
    gemm0_kernel<<<(N_NODES + 63) / 64, dim3(64, 4)>>>(W0, b0);
    bn_coef_kernel<<<1, 64>>>(gammas, betas);

    // layers 1, 2
    for (int l = 0; l < 2; l++) {
        gemm64_kernel<<<(N_NODES + 63) / 64, 256>>>(Ws + (size_t)l * DIM * DIM);
        gather64_kernel<<<N_NODES / 32, 512>>>(bs + (size_t)l * DIM);
        bn_coef_kernel<<<1, 64>>>(gammas + (size_t)(l + 1) * DIM,
                                  betas + (size_t)(l + 1) * DIM);
    }

    // pooling (final BN affine fused) + head
    pool_kernel<<<G_GRAPHS, dim3(64, 4)>>>(batch);
    mlp_kernel<<<G_GRAPHS, 64>>>(lin1_w, lin1_b, lin2_w, lin2_b, out);
}

// round 11
// speedup vs baseline: 2.7548x; 1.0477x over previous
#include <cuda_runtime.h>
#include <math.h>

#define N_NODES 100000
#define N_EDGES 1250000
#define G_GRAPHS 256
#define IN_DIM 8
#define DIM 64
#define EPS 1e-5f
#define NB1 ((N_NODES + 255) / 256)   // 391 scan blocks

// ---------------- scratch (device globals; no allocation allowed) ----------
__device__ float g_deg[N_NODES];
__device__ float g_dinv[N_NODES];
__device__ int   g_cnt[N_NODES];
__device__ int   g_fill[N_NODES];
__device__ int   g_rows[N_NODES];
__device__ int   g_bsum[NB1];
__device__ int   g_rowstart[N_NODES];
__device__ __align__(16) int2  g_csr[N_EDGES];       // {src, val bits}
__device__ __align__(16) float g_t[N_NODES * DIM];   // post-activation (pre-BN)
__device__ __align__(16) float g_h[N_NODES * DIM];   // z = BN(t) @ W
__device__ __align__(16) float g_stats[3 * 2 * DIM]; // per-layer [sum64|sumsq64]

// ---------------- init ----------------
__global__ void init_kernel() {
    int i = blockIdx.x * blockDim.x + threadIdx.x;
    if (i < N_NODES) { g_deg[i] = 1.0f; g_cnt[i] = 0; g_fill[i] = 0; }
    if (blockIdx.x == 0) {
        // cover all 384 stats entries with 256 threads
        for (int k = threadIdx.x; k < 3 * 2 * DIM; k += 256) g_stats[k] = 0.0f;
    }
}

// 2 edges per thread: int2 dst + float4 attrs
__global__ void count_kernel(const int* __restrict__ ei,
                             const float* __restrict__ ea) {
    int i = blockIdx.x * blockDim.x + threadIdx.x;
    if (i < N_EDGES / 2) {
        int2 d = *reinterpret_cast<const int2*>(ei + N_EDGES + 2 * i);
        float4 wv = *reinterpret_cast<const float4*>(ea + 4 * i);
        atomicAdd(&g_cnt[d.x], 1);
        atomicAdd(&g_deg[d.x], wv.y);
        atomicAdd(&g_cnt[d.y], 1);
        atomicAdd(&g_deg[d.y], wv.w);
    }
}

// block-local exclusive scan + block totals + dinv fused
__global__ void scan1_kernel() {
    __shared__ int sdata[256];
    int t = threadIdx.x;
    int n = blockIdx.x * 256 + t;
    int v = (n < N_NODES) ? g_cnt[n] : 0;
    int val = v;
    sdata[t] = val;
    __syncthreads();
    for (int off = 1; off < 256; off <<= 1) {
        int y = (t >= off) ? sdata[t - off] : 0;
        __syncthreads();
        val += y;
        sdata[t] = val;
        __syncthreads();
    }
    if (n < N_NODES) {
        g_rows[n] = val - v;
        float d = g_deg[n];
        g_dinv[n] = (d > 0.0f) ? rsqrtf(d) : 0.0f;
    }
    if (t == 255) g_bsum[blockIdx.x] = val;
}

// each block redundantly computes its bsum prefix, writes final rowstart
__global__ void scan23_kernel() {
    __shared__ int sdata[512];
    __shared__ int rs[256];
    int t = threadIdx.x;
    sdata[t] = (t < NB1) ? g_bsum[t] : 0;
    sdata[t + 256] = (t + 256 < NB1) ? g_bsum[t + 256] : 0;
    __syncthreads();
    int b = blockIdx.x;
    int part = 0;
    if (t < b) part += sdata[t];
    if (t + 256 < b) part += sdata[t + 256];
    rs[t] = part;
    __syncthreads();
    for (int off = 128; off > 0; off >>= 1) {
        if (t < off) rs[t] += rs[t + off];
        __syncthreads();
    }
    int off0 = rs[0];
    int n = b * 256 + t;
    if (n < N_NODES) g_rowstart[n] = g_rows[n] + off0;
}

// 2 edges per thread
__global__ void fill_kernel(const int* __restrict__ ei,
                            const float* __restrict__ ea) {
    int i = blockIdx.x * blockDim.x + threadIdx.x;
    if (i < N_EDGES / 2) {
        int2 s = *reinterpret_cast<const int2*>(ei + 2 * i);
        int2 d = *reinterpret_cast<const int2*>(ei + N_EDGES + 2 * i);
        float4 wv = *reinterpret_cast<const float4*>(ea + 4 * i);
        int p0 = g_rowstart[d.x] + atomicAdd(&g_fill[d.x], 1);
        g_csr[p0] = make_int2(s.x, __float_as_int(g_dinv[s.x] * wv.y));
        int p1 = g_rowstart[d.y] + atomicAdd(&g_fill[d.y], 1);
        g_csr[p1] = make_int2(s.y, __float_as_int(g_dinv[s.y] * wv.w));
    }
}

// ---------------- layer 0 fused: gather x + gemm0 + relu + stats ----------
// 32 nodes per block (exact: 100000 = 3125*32), 256 threads
__global__ void __launch_bounds__(256) l0_kernel(const float* __restrict__ x,
                                                 const float* __restrict__ W0,
                                                 const float* __restrict__ b0) {
    __shared__ float sA[32][IN_DIM];
    __shared__ float sW[IN_DIM][DIM];
    __shared__ float red[4][DIM], red2[4][DIM];
    int tid = threadIdx.x;
    int w = tid >> 5, l = tid & 31;
    int sub = l >> 3, j8 = l & 7;
    for (int i = tid; i < IN_DIM * DIM; i += 256)
        sW[i >> 6][i & 63] = W0[i];
    int nbase = blockIdx.x * 32;
    // gather phase: warp w handles nodes nbase + w*4 + t
    for (int t = 0; t < 4; t++) {
        int ln = w * 4 + t;
        int n = nbase + ln;
        int start = g_rowstart[n];
        int end = start + g_cnt[n];
        float acc = 0.0f;
        for (int e = start + sub; e < end; e += 4) {
            int2 c = g_csr[e];
            acc += __int_as_float(c.y) * x[(size_t)c.x * IN_DIM + j8];
        }
        acc += __shfl_xor_sync(0xffffffffu, acc, 8);
        acc += __shfl_xor_sync(0xffffffffu, acc, 16);
        float di = g_dinv[n];
        if (l < 8) sA[ln][l] = di * acc + di * di * x[(size_t)n * IN_DIM + l];
    }
    __syncthreads();
    // gemm phase: thread (grp, j): 8 nodes x 1 feature
    int j = tid & 63, grp = tid >> 6;
    float bj = b0[j];
    float s = 0.0f, s2 = 0.0f;
    for (int i = 0; i < 8; i++) {
        int ln = grp * 8 + i;
        float acc = bj;
#pragma unroll
        for (int k = 0; k < IN_DIM; k++) acc += sA[ln][k] * sW[k][j];
        float r = fmaxf(acc, 0.0f);
        g_t[(size_t)(nbase + ln) * DIM + j] = r;
        s += r;
        s2 += r * r;
    }
    red[grp][j] = s;
    red2[grp][j] = s2;
    __syncthreads();
    if (tid < 64) {
        atomicAdd(&g_stats[tid], red[0][tid] + red[1][tid] + red[2][tid] + red[3][tid]);
    } else if (tid < 128) {
        int jj = tid - 64;
        atomicAdd(&g_stats[64 + jj],
                  red2[0][jj] + red2[1][jj] + red2[2][jj] + red2[3][jj]);
    }
}

// ---------------- dense layers ----------------
// z[n,j] = sum_k (A[k]*t[n,k]+B[k]) * W[k,j]; BN affine computed in-block
__global__ void gemm64_kernel(const float* __restrict__ W,
                              const float* __restrict__ gamma,
                              const float* __restrict__ beta,
                              int soff) {
    __shared__ float sW[DIM][DIM];
    __shared__ float sH[DIM][DIM];
    __shared__ float sAf[DIM], sBf[DIM];
    int tid = threadIdx.x;           // 256 threads
    int n_base = blockIdx.x * 64;
    if (tid < 64) {
        float mu = g_stats[soff + tid] * (1.0f / N_NODES);
        float var = g_stats[soff + 64 + tid] * (1.0f / N_NODES) - mu * mu;
        float inv = rsqrtf(var + EPS);
        float A = gamma[tid] * inv;
        sAf[tid] = A;
        sBf[tid] = beta[tid] - mu * A;
    }
    for (int i = tid; i < 1024; i += 256)
        reinterpret_cast<float4*>(&sW[0][0])[i] =
            reinterpret_cast<const float4*>(W)[i];
    __syncthreads();
    for (int i = tid; i < 1024; i += 256) {
        int n = i >> 4;
        int k4 = (i & 15) << 2;
        float4 v = make_float4(0.f, 0.f, 0.f, 0.f);
        int row = n_base + n;
        if (row < N_NODES)
            v = reinterpret_cast<const float4*>(g_t + (size_t)row * DIM)[i & 15];
        float4 A = *reinterpret_cast<const float4*>(sAf + k4);
        float4 B = *reinterpret_cast<const float4*>(sBf + k4);
        sH[k4 + 0][n] = A.x * v.x + B.x;
        sH[k4 + 1][n] = A.y * v.y + B.y;
        sH[k4 + 2][n] = A.z * v.z + B.z;
        sH[k4 + 3][n] = A.w * v.w + B.w;
    }
    __syncthreads();
    int tx = tid & 15, ty = tid >> 4;
    int j0 = tx * 4, n0 = ty * 4;
    float acc[4][4];
#pragma unroll
    for (int r = 0; r < 4; r++)
#pragma unroll
        for (int q = 0; q < 4; q++) acc[r][q] = 0.0f;
#pragma unroll
    for (int k = 0; k < DIM; k++) {
        float4 wv = *reinterpret_cast<const float4*>(&sW[k][j0]);
        float4 hv = *reinterpret_cast<const float4*>(&sH[k][n0]);
        acc[0][0] += hv.x * wv.x; acc[0][1] += hv.x * wv.y;
        acc[0][2] += hv.x * wv.z; acc[0][3] += hv.x * wv.w;
        acc[1][0] += hv.y * wv.x; acc[1][1] += hv.y * wv.y;
        acc[1][2] += hv.y * wv.z; acc[1][3] += hv.y * wv.w;
        acc[2][0] += hv.z * wv.x; acc[2][1] += hv.z * wv.y;
        acc[2][2] += hv.z * wv.z; acc[2][3] += hv.z * wv.w;
        acc[3][0] += hv.w * wv.x; acc[3][1] += hv.w * wv.y;
        acc[3][2] += hv.w * wv.z; acc[3][3] += hv.w * wv.w;
    }
#pragma unroll
    for (int r = 0; r < 4; r++) {
        int row = n_base + n0 + r;
        if (row < N_NODES) {
            float4 o = make_float4(acc[r][0], acc[r][1], acc[r][2], acc[r][3]);
            *reinterpret_cast<float4*>(g_h + (size_t)row * DIM + j0) = o;
        }
    }
}

// gather + self-loop + bias + relu + stats; warp per node (4 nodes sequential),
// lane l handles features {2l, 2l+1}. 256 thr = 8 warps = 32 nodes/block.
__global__ void __launch_bounds__(256) gather64_kernel(const float* __restrict__ bias,
                                                       int soff) {
    int tid = threadIdx.x;
    int w = tid >> 5, l = tid & 31;
    float2 bvec = *reinterpret_cast<const float2*>(bias + 2 * l);
    float sx = 0.f, sy = 0.f, qx = 0.f, qy = 0.f;
    int nbase = blockIdx.x * 32 + w * 4;
    for (int t = 0; t < 4; t++) {
        int n = nbase + t;
        int start = g_rowstart[n];
        int end = start + g_cnt[n];
        float ax = 0.f, ay = 0.f;
        int e = start;
        for (; e + 4 <= end; e += 4) {
            int2 c0 = g_csr[e],     c1 = g_csr[e + 1];
            int2 c2 = g_csr[e + 2], c3 = g_csr[e + 3];
            float2 h0 = *reinterpret_cast<const float2*>(g_h + (size_t)c0.x * DIM + 2 * l);
            float2 h1 = *reinterpret_cast<const float2*>(g_h + (size_t)c1.x * DIM + 2 * l);
            float2 h2 = *reinterpret_cast<const float2*>(g_h + (size_t)c2.x * DIM + 2 * l);
            float2 h3 = *reinterpret_cast<const float2*>(g_h + (size_t)c3.x * DIM + 2 * l);
            float v0 = __int_as_float(c0.y), v1 = __int_as_float(c1.y);
            float v2 = __int_as_float(c2.y), v3 = __int_as_float(c3.y);
            ax += v0 * h0.x + v1 * h1.x + v2 * h2.x + v3 * h3.x;
            ay += v0 * h0.y + v1 * h1.y + v2 * h2.y + v3 * h3.y;
        }
        for (; e < end; e++) {
            int2 c0 = g_csr[e];
            float v0 = __int_as_float(c0.y);
            float2 h0 = *reinterpret_cast<const float2*>(g_h + (size_t)c0.x * DIM + 2 * l);
            ax += v0 * h0.x;
            ay += v0 * h0.y;
        }
        float di = g_dinv[n], di2 = di * di;
        float2 self = *reinterpret_cast<const float2*>(g_h + (size_t)n * DIM + 2 * l);
        float rx = fmaxf(di * ax + di2 * self.x + bvec.x, 0.f);
        float ry = fmaxf(di * ay + di2 * self.y + bvec.y, 0.f);
        *reinterpret_cast<float2*>(g_t + (size_t)n * DIM + 2 * l) = make_float2(rx, ry);
        sx += rx; sy += ry;
        qx += rx * rx; qy += ry * ry;
    }
    __shared__ float ss[8][DIM], sq[8][DIM];
    ss[w][2 * l] = sx; ss[w][2 * l + 1] = sy;
    sq[w][2 * l] = qx; sq[w][2 * l + 1] = qy;
    __syncthreads();
    if (tid < 64) {
        float s = 0.f;
#pragma unroll
        for (int i = 0; i < 8; i++) s += ss[i][tid];
        atomicAdd(&g_stats[soff + tid], s);
    } else if (tid < 128) {
        int jj = tid - 64;
        float s = 0.f;
#pragma unroll
        for (int i = 0; i < 8; i++) s += sq[i][jj];
        atomicAdd(&g_stats[soff + 64 + jj], s);
    }
}

// ---------------- pooling (final BN affine) + MLP head fused ----------------
__global__ void poolmlp_kernel(const int* __restrict__ batch,
                               const float* __restrict__ gamma,
                               const float* __restrict__ beta,
                               const float* __restrict__ lin1_w,
                               const float* __restrict__ lin1_b,
                               const float* __restrict__ lin2_w,
                               const float* __restrict__ lin2_b,
                               float* __restrict__ out) {
    int g = blockIdx.x;
    int j = threadIdx.x;   // 0..63
    int ty = threadIdx.y;  // 0..3
    int lo = 0, hi = N_NODES;
    while (lo < hi) { int m = (lo + hi) >> 1; if (batch[m] < g) lo = m + 1; else hi = m; }
    int start = lo;
    lo = start; hi = N_NODES;
    while (lo < hi) { int m = (lo + hi) >> 1; if (batch[m] < g + 1) lo = m + 1; else hi = m; }
    int end = lo;
    float acc = 0.0f;
    for (int i = start + ty; i < end; i += 4) acc += g_t[(size_t)i * DIM + j];
    __shared__ float sh4[4][DIM];
    __shared__ float sp[DIM];
    __shared__ float sh[DIM];
    sh4[ty][j] = acc;
    __syncthreads();
    if (ty == 0) {
        float s = sh4[0][j] + sh4[1][j] + sh4[2][j] + sh4[3][j];
        float mu = g_stats[256 + j] * (1.0f / N_NODES);
        float var = g_stats[256 + 64 + j] * (1.0f / N_NODES) - mu * mu;
        float inv = rsqrtf(var + EPS);
        float A = gamma[j] * inv;
        float B = beta[j] - mu * A;
        sp[j] = A * s + B * (float)(end - start);
    }
    __syncthreads();
    // lin1 partial over k-range
    float a1 = 0.0f;
#pragma unroll
    for (int k = ty * 16; k < ty * 16 + 16; k++) a1 += sp[k] * lin1_w[k * DIM + j];
    sh4[ty][j] = a1;
    __syncthreads();
    if (ty == 0)
        sh[j] = fmaxf(sh4[0][j] + sh4[1][j] + sh4[2][j] + sh4[3][j] + lin1_b[j], 0.0f);
    __syncthreads();
    if (j == 0 && ty == 0) {
        float o0 = lin2_b[0], o1 = lin2_b[1];
#pragma unroll
        for (int k = 0; k < DIM; k++) {
            o0 += sh[k] * lin2_w[k * 2 + 0];
            o1 += sh[k] * lin2_w[k * 2 + 1];
        }
        float m = fmaxf(o0, o1);
        float lse = m + logf(expf(o0 - m) + expf(o1 - m));
        out[g * 2 + 0] = o0 - lse;
        out[g * 2 + 1] = o1 - lse;
    }
}

// ---------------- launch ----------------
extern "C" void kernel_launch(void* const* d_in, const int* in_sizes, int n_in,
                              void* d_out, int out_size) {
    const float* x        = (const float*)d_in[0];
    const int*   ei       = (const int*)d_in[1];
    const int*   batch    = (const int*)d_in[2];
    const float* ea       = (const float*)d_in[3];
    const float* W0       = (const float*)d_in[4];
    const float* b0       = (const float*)d_in[5];
    const float* Ws       = (const float*)d_in[6];
    const float* bs       = (const float*)d_in[7];
    const float* gammas   = (const float*)d_in[8];
    const float* betas    = (const float*)d_in[9];
    const float* lin1_w   = (const float*)d_in[10];
    const float* lin1_b   = (const float*)d_in[11];
    const float* lin2_w   = (const float*)d_in[12];
    const float* lin2_b   = (const float*)d_in[13];
    float* out = (float*)d_out;

    const int TB = 256;
    const int EB2 = (N_EDGES / 2 + TB - 1) / TB;

    // CSR build + normalization
    init_kernel<<<NB1, TB>>>();
    count_kernel<<<EB2, TB>>>(ei, ea);
    scan1_kernel<<<NB1, TB>>>();
    scan23_kernel<<<NB1, TB>>>();
    fill_kernel<<<EB2, TB>>>(ei, ea);

    // layer 0 fused (stats -> slot 0)
    l0_kernel<<<N_NODES / 32, TB>>>(x, W0, b0);

    // layers 1, 2
    for (int l = 0; l < 2; l++) {
        gemm64_kernel<<<(N_NODES + 63) / 64, 256>>>(
            Ws + (size_t)l * DIM * DIM, gammas + (size_t)l * DIM,
            betas + (size_t)l * DIM, l * 128);
        gather64_kernel<<<N_NODES / 32, 256>>>(bs + (size_t)l * DIM, (l + 1) * 128);
    }

    // pooling (BN slot 2 fused) + head
    poolmlp_kernel<<<G_GRAPHS, dim3(64, 4)>>>(batch, gammas + 2 * DIM, betas + 2 * DIM,
                                              lin1_w, lin1_b, lin2_w, lin2_b, out);
}